// round 15
// baseline (speedup 1.0000x reference)
#include <cuda_runtime.h>
#include <cuda_fp16.h>
#include <cstdint>
#include <math.h>

#define BB   2
#define HH   64
#define WW   64
#define CC   256
#define NHE  8
#define HDIM 32
#define KWIN 7
#define NPIX (BB*HH*WW)   // 8192

// ---------------- scratch (no allocation allowed) ----------------
__device__ __align__(16) __half g_xn  [NPIX * CC];
__device__ float               g_qkv [NPIX * 3 * CC];
__device__ __align__(16) __half g_attn[NPIX * CC];
__device__ __align__(16) __half g_hn  [NPIX * CC];
__device__ __align__(16) __half g_h1  [NPIX * 4 * CC];
__device__ __align__(16) __half g_wh  [12 * CC * CC];   // fp16 weights: qkv|proj|fc1|fc2

// ======================= PTX helpers (sm_80-era only; target is plain sm_103) ===============
__device__ __forceinline__ uint32_t smem_u32(const void* p) {
    uint32_t a;
    asm("{ .reg .u64 t; cvta.to.shared.u64 t, %1; cvt.u32.u64 %0, t; }" : "=r"(a) : "l"(p));
    return a;
}

#define CP_ASYNC16(dst, src) \
    asm volatile("cp.async.cg.shared.global [%0], [%1], 16;" :: "r"(dst), "l"(src) : "memory")
#define CP_COMMIT()  asm volatile("cp.async.commit_group;" ::: "memory")
#define CP_WAIT(n)   asm volatile("cp.async.wait_group %0;" :: "n"(n) : "memory")

__device__ __forceinline__ void ldsm_x4(uint32_t* r, uint32_t addr) {
    asm volatile("ldmatrix.sync.aligned.m8n8.x4.shared.b16 {%0,%1,%2,%3}, [%4];"
                 : "=r"(r[0]), "=r"(r[1]), "=r"(r[2]), "=r"(r[3]) : "r"(addr));
}

__device__ __forceinline__ void mma_f16(float* c, const uint32_t* a, const uint32_t* b) {
    asm volatile("mma.sync.aligned.m16n8k16.row.col.f32.f16.f16.f32 "
                 "{%0,%1,%2,%3}, {%4,%5,%6,%7}, {%8,%9}, {%0,%1,%2,%3};"
                 : "+f"(c[0]), "+f"(c[1]), "+f"(c[2]), "+f"(c[3])
                 : "r"(a[0]), "r"(a[1]), "r"(a[2]), "r"(a[3]), "r"(b[0]), "r"(b[1]));
}

// fp16 SMEM tile: rows x 32 halfs (64B data), padded to 80B pitch.
#define TPH      80
#define TILE_A_H (128 * TPH)                          // 10240 B

// ---------------- convert weights to fp16 (RN) ----------------
// concatenated float4 ranges: qkv 49152 | proj 16384 | fc1 65536 | fc2 65536
__global__ void round_weights(const float4* __restrict__ w0,
                              const float4* __restrict__ w1,
                              const float4* __restrict__ w2,
                              const float4* __restrict__ w3,
                              __half2* __restrict__ out) {
    int i = blockIdx.x * 256 + threadIdx.x;     // 0 .. 196607
    const float4* src;
    int off;
    if      (i <  49152) { src = w0; off = 0;      }
    else if (i <  65536) { src = w1; off = 49152;  }
    else if (i < 131072) { src = w2; off = 65536;  }
    else                 { src = w3; off = 131072; }
    float4 v = src[i - off];
    out[2 * i]     = __floats2half2_rn(v.x, v.y);
    out[2 * i + 1] = __floats2half2_rn(v.z, v.w);
}

// ============ fp16 m16n8k16 GEMM, 3-stage pipeline ============
// out[M,N] = A[M,K] * W[N,K]^T + bias (+res/+gelu).  Tile: 128 x BN (BN in {128, 64}).
// EPI: 0 = bias, 1 = bias + residual, 2 = bias + exact GELU
// OUTH: 0 = fp32 output, 1 = fp16 output
template <int EPI, int BN, int OUTH>
__global__ void __launch_bounds__(256, 2)
gemm_tc(const __half* __restrict__ A,
        const __half* __restrict__ Wm,
        const float* __restrict__ bias,
        const float* __restrict__ res,
        void* __restrict__ outv,
        int M, int N, int Kd) {
    constexpr int WN    = BN / 32;        // warps along N
    constexpr int WM    = 8 / WN;         // warps along M
    constexpr int MT    = 128 / (16 * WM);// m16 tiles per warp
    constexpr int STAGE = TILE_A_H + BN * TPH;

    extern __shared__ __align__(1024) char smem[];
    const uint32_t sb = smem_u32(smem);

    const int tid  = threadIdx.x;
    const int wid  = tid >> 5;
    const int lane = tid & 31;
    const int wm   = wid / WN;
    const int wn   = wid % WN;
    const int m0   = blockIdx.y * 128;
    const int n0   = blockIdx.x * BN;
    const int niters = Kd >> 5;           // K slabs of 32 halfs (64B)

    const int sub = lane >> 3;
    const int mr  = lane & 7;
    const uint32_t aoff = (uint32_t)((wm * (MT * 16) + (sub & 1) * 8 + mr) * TPH + (sub >> 1) * 16);
    const uint32_t boff = (uint32_t)(TILE_A_H + (wn * 32 + (sub >> 1) * 8 + mr) * TPH + (sub & 1) * 16);

    float acc[MT][4][4];
    #pragma unroll
    for (int i = 0; i < MT; i++)
        #pragma unroll
        for (int j = 0; j < 4; j++)
            #pragma unroll
            for (int k = 0; k < 4; k++) acc[i][j][k] = 0.0f;

    auto load_stage = [&](int it, int s) {
        const uint32_t base = sb + s * STAGE;
        #pragma unroll
        for (int idx = 0; idx < 2; idx++) {
            const int t = tid + idx * 256;        // 0..511 (128 rows x 4 chunks)
            const int row = t >> 2, c = t & 3;
            CP_ASYNC16(base + row * TPH + c * 16,
                       A + (size_t)(m0 + row) * Kd + it * 32 + c * 8);
        }
        #pragma unroll
        for (int idx = 0; idx < BN / 64; idx++) {
            const int t = tid + idx * 256;        // 0..BN*4-1
            const int row = t >> 2, c = t & 3;
            CP_ASYNC16(base + TILE_A_H + row * TPH + c * 16,
                       Wm + (size_t)(n0 + row) * Kd + it * 32 + c * 8);
        }
    };

    load_stage(0, 0); CP_COMMIT();
    load_stage(1, 1); CP_COMMIT();

    for (int it = 0; it < niters; it++) {
        const int s = it - (it / 3) * 3;
        CP_WAIT(1);                 // stage `it` resident
        __syncthreads();
        const int p = it + 2;
        if (p < niters) load_stage(p, p - (p / 3) * 3);
        CP_COMMIT();

        const uint32_t Ab = sb + s * STAGE;

        #pragma unroll
        for (int ks = 0; ks < 2; ks++) {          // two k16 steps per 32-half slab
            uint32_t af[MT][4];
            #pragma unroll
            for (int mt = 0; mt < MT; mt++)
                ldsm_x4(af[mt], Ab + aoff + mt * (16 * TPH) + ks * 32);
            uint32_t bf[8];
            #pragma unroll
            for (int pp = 0; pp < 2; pp++)
                ldsm_x4(&bf[pp * 4], Ab + boff + pp * (16 * TPH) + ks * 32);
            #pragma unroll
            for (int mt = 0; mt < MT; mt++)
                #pragma unroll
                for (int nt = 0; nt < 4; nt++)
                    mma_f16(acc[mt][nt], af[mt], &bf[(nt >> 1) * 4 + (nt & 1) * 2]);
        }
    }
    __syncthreads();

    float*  outf = (float*)outv;
    __half* outh = (__half*)outv;
    const int gid = lane >> 2;
    const int tig = lane & 3;
    #pragma unroll
    for (int nt = 0; nt < 4; nt++) {
        const int n = n0 + wn * 32 + nt * 8 + 2 * tig;
        const float2 bn = *(const float2*)(bias + n);
        #pragma unroll
        for (int mt = 0; mt < MT; mt++) {
            const int r0 = m0 + wm * (MT * 16) + mt * 16 + gid;
            const int r1 = r0 + 8;
            float v0 = acc[mt][nt][0] + bn.x;
            float v1 = acc[mt][nt][1] + bn.y;
            float v2 = acc[mt][nt][2] + bn.x;
            float v3 = acc[mt][nt][3] + bn.y;
            if (EPI == 1) {
                const float2 q0 = *(const float2*)(res + (size_t)r0 * N + n);
                const float2 q1 = *(const float2*)(res + (size_t)r1 * N + n);
                v0 += q0.x; v1 += q0.y; v2 += q1.x; v3 += q1.y;
            }
            if (EPI == 2) {
                v0 = 0.5f * v0 * (1.0f + erff(v0 * 0.70710678118654752f));
                v1 = 0.5f * v1 * (1.0f + erff(v1 * 0.70710678118654752f));
                v2 = 0.5f * v2 * (1.0f + erff(v2 * 0.70710678118654752f));
                v3 = 0.5f * v3 * (1.0f + erff(v3 * 0.70710678118654752f));
            }
            if (OUTH) {
                *(__half2*)(outh + (size_t)r0 * N + n) = __floats2half2_rn(v0, v1);
                *(__half2*)(outh + (size_t)r1 * N + n) = __floats2half2_rn(v2, v3);
            } else {
                *(float2*)(outf + (size_t)r0 * N + n) = make_float2(v0, v1);
                *(float2*)(outf + (size_t)r1 * N + n) = make_float2(v2, v3);
            }
        }
    }
}

// ---------------- LayerNorm (fp32 in, fp16 out: feeds a GEMM only) ----------------
__global__ void ln_kernel(const float* __restrict__ x,
                          const float* __restrict__ w,
                          const float* __restrict__ b,
                          __half* __restrict__ out) {
    int row = blockIdx.x;
    int t = threadIdx.x;
    float v = x[row * CC + t];
    __shared__ float s1[256];
    __shared__ float s2[256];
    s1[t] = v; s2[t] = v * v;
    __syncthreads();
    #pragma unroll
    for (int off = 128; off > 0; off >>= 1) {
        if (t < off) { s1[t] += s1[t + off]; s2[t] += s2[t + off]; }
        __syncthreads();
    }
    float m   = s1[0] * (1.0f / CC);
    float var = s2[0] * (1.0f / CC) - m * m;
    float r   = rsqrtf(var + 1e-5f);
    out[row * CC + t] = __float2half_rn((v - m) * r * w[t] + b[t]);
}

// ---------------- tiled neighborhood attention (R10: fp32 halos, fp32 compute) ----------------
// 128 blocks (one full wave), 512 threads; block = (16x16 tile, head PAIR, batch).
// Lane pairs (tx, tx+16) split the 32 head channels; one shfl combines scores.
#define TS    16
#define HALO  22          // TS + 6
#define NHPIX (HALO*HALO) // 484
#define PPITCH 36         // floats per halo pixel (32 data + 4 pad: bank spread)
#define NATT_SMEM (2 * NHPIX * PPITCH * 4)   // 139392 B

__global__ void __launch_bounds__(512)
natt_tile(const float* __restrict__ qkv, __half* __restrict__ out) {
    extern __shared__ float sm[];
    float* ks = sm;
    float* vs = sm + NHPIX * PPITCH;

    const int tile  = blockIdx.x;         // 0..15 (4x4 tiles)
    const int hpair = blockIdx.y;         // 0..3
    const int b     = blockIdx.z;
    const int ti0 = (tile >> 2) * TS;
    const int tj0 = (tile & 3) * TS;
    const int tid = threadIdx.x;

    const int lane = tid & 31;
    const int tx   = lane & 15;
    const int half = lane >> 4;           // channel half: 0 or 1
    const int ty   = tid >> 5;            // 0..15
    const int choff = half * 16;          // channel offset within head

    const int hbr = ti0 - 3;
    const int hbc = tj0 - 3;
    const int i = ti0 + ty;
    const int j = tj0 + tx;
    const size_t pix = (size_t)((b * HH + i) * WW + j);

    const int si = min(max(i - 3, 0), HH - KWIN);
    const int sj = min(max(j - 3, 0), WW - KWIN);
    const int lr0 = si - hbr;
    const int lc0 = sj - hbc;

    #pragma unroll
    for (int hp = 0; hp < 2; hp++) {
        const int head  = hpair * 2 + hp;
        const int hbase = head * HDIM;

        // ---- stage K and V halos for this head ----
        for (int idx = tid; idx < NHPIX * 8; idx += 512) {
            const int p  = idx >> 3;
            const int c  = idx & 7;
            const int hr = p / HALO;
            const int hc = p - hr * HALO;
            const int gr = min(max(hbr + hr, 0), HH - 1);
            const int gc = min(max(hbc + hc, 0), WW - 1);
            const size_t gpix = (size_t)((b * HH + gr) * WW + gc);
            const float* base = qkv + gpix * 768 + hbase;
            *(float4*)(ks + p * PPITCH + c * 4) = *(const float4*)(base + 256 + c * 4);
            *(float4*)(vs + p * PPITCH + c * 4) = *(const float4*)(base + 512 + c * 4);
        }

        // ---- q (this thread's 16 channels), pre-scaled; overlaps staging ----
        float4 q[4];
        const float4* qp = (const float4*)(qkv + pix * 768 + hbase + choff);
        #pragma unroll
        for (int c = 0; c < 4; c++) {
            q[c] = qp[c];
            q[c].x *= 0.17677669529663687f; q[c].y *= 0.17677669529663687f;
            q[c].z *= 0.17677669529663687f; q[c].w *= 0.17677669529663687f;
        }
        __syncthreads();

        // ---- QK: 49 half-scores, then pairwise combine via 1 shuffle each ----
        float sc[49];
        #pragma unroll
        for (int dr = 0; dr < 7; dr++) {
            const float* rowp = ks + (lr0 + dr) * (HALO * PPITCH) + lc0 * PPITCH + choff;
            #pragma unroll
            for (int dc = 0; dc < 7; dc++) {
                const float* kp = rowp + dc * PPITCH;
                float d0 = 0.f, d1 = 0.f, d2 = 0.f, d3 = 0.f;
                #pragma unroll
                for (int c = 0; c < 4; c++) {
                    float4 kv = *(const float4*)(kp + c * 4);
                    d0 = fmaf(q[c].x, kv.x, d0);
                    d1 = fmaf(q[c].y, kv.y, d1);
                    d2 = fmaf(q[c].z, kv.z, d2);
                    d3 = fmaf(q[c].w, kv.w, d3);
                }
                sc[dr * 7 + dc] = (d0 + d1) + (d2 + d3);
            }
        }
        #pragma unroll
        for (int n = 0; n < 49; n++)
            sc[n] += __shfl_xor_sync(0xFFFFFFFFu, sc[n], 16);

        // ---- softmax (in-thread; redundant across the lane pair) ----
        float m = sc[0];
        #pragma unroll
        for (int n = 1; n < 49; n++) m = fmaxf(m, sc[n]);
        float den = 0.f;
        #pragma unroll
        for (int n = 0; n < 49; n++) { sc[n] = __expf(sc[n] - m); den += sc[n]; }
        const float inv = 1.0f / den;

        // ---- AV over this thread's 16 channels ----
        float4 acc[4];
        #pragma unroll
        for (int c = 0; c < 4; c++) acc[c] = make_float4(0.f, 0.f, 0.f, 0.f);
        #pragma unroll
        for (int dr = 0; dr < 7; dr++) {
            const float* rowp = vs + (lr0 + dr) * (HALO * PPITCH) + lc0 * PPITCH + choff;
            #pragma unroll
            for (int dc = 0; dc < 7; dc++) {
                const float w = sc[dr * 7 + dc];
                const float* vp = rowp + dc * PPITCH;
                #pragma unroll
                for (int c = 0; c < 4; c++) {
                    float4 vv = *(const float4*)(vp + c * 4);
                    acc[c].x = fmaf(w, vv.x, acc[c].x);
                    acc[c].y = fmaf(w, vv.y, acc[c].y);
                    acc[c].z = fmaf(w, vv.z, acc[c].z);
                    acc[c].w = fmaf(w, vv.w, acc[c].w);
                }
            }
        }

        __half2* op = (__half2*)(out + pix * CC + hbase + choff);
        #pragma unroll
        for (int c = 0; c < 4; c++) {
            op[2 * c]     = __floats2half2_rn(acc[c].x * inv, acc[c].y * inv);
            op[2 * c + 1] = __floats2half2_rn(acc[c].z * inv, acc[c].w * inv);
        }
        if (hp == 0) __syncthreads();   // all reads done before restaging
    }
}

// ---------------- host launcher ----------------
extern "C" void kernel_launch(void* const* d_in, const int* in_sizes, int n_in,
                              void* d_out, int out_size) {
    const float* x      = (const float*)d_in[0];
    const float* ln1_w  = (const float*)d_in[1];
    const float* ln1_b  = (const float*)d_in[2];
    const float* qkv_w  = (const float*)d_in[3];
    const float* qkv_b  = (const float*)d_in[4];
    const float* proj_w = (const float*)d_in[5];
    const float* proj_b = (const float*)d_in[6];
    const float* ln2_w  = (const float*)d_in[7];
    const float* ln2_b  = (const float*)d_in[8];
    const float* fc1_w  = (const float*)d_in[9];
    const float* fc1_b  = (const float*)d_in[10];
    const float* fc2_w  = (const float*)d_in[11];
    const float* fc2_b  = (const float*)d_in[12];
    float* out = (float*)d_out;

    __half *xn, *attn, *hn, *h1, *wh;
    float *qkv;
    cudaGetSymbolAddress((void**)&xn,   g_xn);
    cudaGetSymbolAddress((void**)&qkv,  g_qkv);
    cudaGetSymbolAddress((void**)&attn, g_attn);
    cudaGetSymbolAddress((void**)&hn,   g_hn);
    cudaGetSymbolAddress((void**)&h1,   g_h1);
    cudaGetSymbolAddress((void**)&wh,   g_wh);

    const __half* wh_qkv  = wh;                      // 196608 halfs
    const __half* wh_proj = wh + 196608;             // 65536
    const __half* wh_fc1  = wh + 262144;             // 262144
    const __half* wh_fc2  = wh + 524288;             // 262144

    constexpr int SM128 = 3 * (TILE_A_H + 128 * TPH);  // 61440
    constexpr int SM64  = 3 * (TILE_A_H + 64  * TPH);  // 46080

    cudaFuncSetAttribute((const void*)gemm_tc<0,64,0>,  cudaFuncAttributeMaxDynamicSharedMemorySize, SM64);
    cudaFuncSetAttribute((const void*)gemm_tc<2,128,1>, cudaFuncAttributeMaxDynamicSharedMemorySize, SM128);
    cudaFuncSetAttribute((const void*)gemm_tc<1,64,0>,  cudaFuncAttributeMaxDynamicSharedMemorySize, SM64);
    cudaFuncSetAttribute((const void*)natt_tile,        cudaFuncAttributeMaxDynamicSharedMemorySize, NATT_SMEM);

    // 0. convert all weights to fp16 (RN)
    round_weights<<<768, 256>>>((const float4*)qkv_w, (const float4*)proj_w,
                                (const float4*)fc1_w, (const float4*)fc2_w,
                                (__half2*)wh);

    // 1. LN1 -> fp16
    ln_kernel<<<NPIX, 256>>>(x, ln1_w, ln1_b, xn);

    // 2. QKV GEMM: [8192,256] x [768,256]^T -> fp32   (BN=64: 768 blocks, better balance)
    gemm_tc<0,64,0><<<dim3(768 / 64, NPIX / 128), 256, SM64>>>(
        xn, wh_qkv, qkv_b, nullptr, qkv, NPIX, 768, CC);

    // 3. tiled neighborhood attention (R10 kernel) -> fp16
    natt_tile<<<dim3(16, NHE / 2, BB), 512, NATT_SMEM>>>(qkv, attn);

    // 4. proj GEMM + bias + residual(x) -> fp32 d_out   (BN=64: 256 blocks)
    gemm_tc<1,64,0><<<dim3(CC / 64, NPIX / 128), 256, SM64>>>(
        attn, wh_proj, proj_b, x, out, NPIX, CC, CC);

    // 5. LN2 -> fp16
    ln_kernel<<<NPIX, 256>>>(out, ln2_w, ln2_b, hn);

    // 6. fc1 GEMM + exact GELU -> fp16
    gemm_tc<2,128,1><<<dim3(1024 / 128, NPIX / 128), 256, SM128>>>(
        hn, wh_fc1, fc1_b, nullptr, h1, NPIX, 1024, CC);

    // 7. fc2 GEMM + bias + residual(d_out) -> fp32 d_out   (BN=64: 256 blocks)
    gemm_tc<1,64,0><<<dim3(CC / 64, NPIX / 128), 256, SM64>>>(
        h1, wh_fc2, fc2_b, out, out, NPIX, CC, 1024);
}

// round 16
// speedup vs baseline: 1.1898x; 1.1898x over previous
#include <cuda_runtime.h>
#include <cuda_fp16.h>
#include <cstdint>
#include <math.h>

#define BB   2
#define HH   64
#define WW   64
#define CC   256
#define NHE  8
#define HDIM 32
#define KWIN 7
#define NPIX (BB*HH*WW)   // 8192

// ---------------- scratch (no allocation allowed) ----------------
__device__ __align__(16) __half g_xn  [NPIX * CC];
__device__ float               g_qkv [NPIX * 3 * CC];
__device__ __align__(16) __half g_attn[NPIX * CC];
__device__ __align__(16) __half g_hn  [NPIX * CC];
__device__ __align__(16) __half g_h1  [NPIX * 4 * CC];
__device__ __align__(16) __half g_wh  [12 * CC * CC];   // fp16 weights: qkv|proj|fc1|fc2

// ======================= PTX helpers (sm_80-era only; target is plain sm_103) ===============
__device__ __forceinline__ uint32_t smem_u32(const void* p) {
    uint32_t a;
    asm("{ .reg .u64 t; cvta.to.shared.u64 t, %1; cvt.u32.u64 %0, t; }" : "=r"(a) : "l"(p));
    return a;
}

#define CP_ASYNC16(dst, src) \
    asm volatile("cp.async.cg.shared.global [%0], [%1], 16;" :: "r"(dst), "l"(src) : "memory")
#define CP_COMMIT()  asm volatile("cp.async.commit_group;" ::: "memory")
#define CP_WAIT(n)   asm volatile("cp.async.wait_group %0;" :: "n"(n) : "memory")

__device__ __forceinline__ void ldsm_x4(uint32_t* r, uint32_t addr) {
    asm volatile("ldmatrix.sync.aligned.m8n8.x4.shared.b16 {%0,%1,%2,%3}, [%4];"
                 : "=r"(r[0]), "=r"(r[1]), "=r"(r[2]), "=r"(r[3]) : "r"(addr));
}

__device__ __forceinline__ void mma_f16(float* c, const uint32_t* a, const uint32_t* b) {
    asm volatile("mma.sync.aligned.m16n8k16.row.col.f32.f16.f16.f32 "
                 "{%0,%1,%2,%3}, {%4,%5,%6,%7}, {%8,%9}, {%0,%1,%2,%3};"
                 : "+f"(c[0]), "+f"(c[1]), "+f"(c[2]), "+f"(c[3])
                 : "r"(a[0]), "r"(a[1]), "r"(a[2]), "r"(a[3]), "r"(b[0]), "r"(b[1]));
}

__device__ __forceinline__ uint32_t pack_h2(float x, float y) {
    __half2 h = __floats2half2_rn(x, y);
    return *(uint32_t*)&h;
}

// fp16 SMEM tile: rows x 32 halfs (64B data), padded to 80B pitch.
#define TPH      80
#define TILE_A_H (128 * TPH)                          // 10240 B

// ---------------- convert weights to fp16 (RN) ----------------
// concatenated float4 ranges: qkv 49152 | proj 16384 | fc1 65536 | fc2 65536
__global__ void round_weights(const float4* __restrict__ w0,
                              const float4* __restrict__ w1,
                              const float4* __restrict__ w2,
                              const float4* __restrict__ w3,
                              __half2* __restrict__ out) {
    int i = blockIdx.x * 256 + threadIdx.x;     // 0 .. 196607
    const float4* src;
    int off;
    if      (i <  49152) { src = w0; off = 0;      }
    else if (i <  65536) { src = w1; off = 49152;  }
    else if (i < 131072) { src = w2; off = 65536;  }
    else                 { src = w3; off = 131072; }
    float4 v = src[i - off];
    out[2 * i]     = __floats2half2_rn(v.x, v.y);
    out[2 * i + 1] = __floats2half2_rn(v.z, v.w);
}

// ============ fp16 m16n8k16 GEMM, 3-stage pipeline ============
// out[M,N] = A[M,K] * W[N,K]^T + bias (+res/+gelu).  Tile: 128 x BN (BN in {128, 64}).
// EPI: 0 = bias, 1 = bias + residual, 2 = bias + exact GELU
// OUTH: 0 = fp32 output, 1 = fp16 output
template <int EPI, int BN, int OUTH>
__global__ void __launch_bounds__(256, 2)
gemm_tc(const __half* __restrict__ A,
        const __half* __restrict__ Wm,
        const float* __restrict__ bias,
        const float* __restrict__ res,
        void* __restrict__ outv,
        int M, int N, int Kd) {
    constexpr int WN    = BN / 32;        // warps along N
    constexpr int WM    = 8 / WN;         // warps along M
    constexpr int MT    = 128 / (16 * WM);// m16 tiles per warp
    constexpr int STAGE = TILE_A_H + BN * TPH;

    extern __shared__ __align__(1024) char smem[];
    const uint32_t sb = smem_u32(smem);

    const int tid  = threadIdx.x;
    const int wid  = tid >> 5;
    const int lane = tid & 31;
    const int wm   = wid / WN;
    const int wn   = wid % WN;
    const int m0   = blockIdx.y * 128;
    const int n0   = blockIdx.x * BN;
    const int niters = Kd >> 5;           // K slabs of 32 halfs (64B)

    const int sub = lane >> 3;
    const int mr  = lane & 7;
    const uint32_t aoff = (uint32_t)((wm * (MT * 16) + (sub & 1) * 8 + mr) * TPH + (sub >> 1) * 16);
    const uint32_t boff = (uint32_t)(TILE_A_H + (wn * 32 + (sub >> 1) * 8 + mr) * TPH + (sub & 1) * 16);

    float acc[MT][4][4];
    #pragma unroll
    for (int i = 0; i < MT; i++)
        #pragma unroll
        for (int j = 0; j < 4; j++)
            #pragma unroll
            for (int k = 0; k < 4; k++) acc[i][j][k] = 0.0f;

    auto load_stage = [&](int it, int s) {
        const uint32_t base = sb + s * STAGE;
        #pragma unroll
        for (int idx = 0; idx < 2; idx++) {
            const int t = tid + idx * 256;        // 0..511 (128 rows x 4 chunks)
            const int row = t >> 2, c = t & 3;
            CP_ASYNC16(base + row * TPH + c * 16,
                       A + (size_t)(m0 + row) * Kd + it * 32 + c * 8);
        }
        #pragma unroll
        for (int idx = 0; idx < BN / 64; idx++) {
            const int t = tid + idx * 256;        // 0..BN*4-1
            const int row = t >> 2, c = t & 3;
            CP_ASYNC16(base + TILE_A_H + row * TPH + c * 16,
                       Wm + (size_t)(n0 + row) * Kd + it * 32 + c * 8);
        }
    };

    load_stage(0, 0); CP_COMMIT();
    load_stage(1, 1); CP_COMMIT();

    for (int it = 0; it < niters; it++) {
        const int s = it - (it / 3) * 3;
        CP_WAIT(1);                 // stage `it` resident
        __syncthreads();
        const int p = it + 2;
        if (p < niters) load_stage(p, p - (p / 3) * 3);
        CP_COMMIT();

        const uint32_t Ab = sb + s * STAGE;

        #pragma unroll
        for (int ks = 0; ks < 2; ks++) {          // two k16 steps per 32-half slab
            uint32_t af[MT][4];
            #pragma unroll
            for (int mt = 0; mt < MT; mt++)
                ldsm_x4(af[mt], Ab + aoff + mt * (16 * TPH) + ks * 32);
            uint32_t bf[8];
            #pragma unroll
            for (int pp = 0; pp < 2; pp++)
                ldsm_x4(&bf[pp * 4], Ab + boff + pp * (16 * TPH) + ks * 32);
            #pragma unroll
            for (int mt = 0; mt < MT; mt++)
                #pragma unroll
                for (int nt = 0; nt < 4; nt++)
                    mma_f16(acc[mt][nt], af[mt], &bf[(nt >> 1) * 4 + (nt & 1) * 2]);
        }
    }
    __syncthreads();

    float*  outf = (float*)outv;
    __half* outh = (__half*)outv;
    const int gid = lane >> 2;
    const int tig = lane & 3;
    #pragma unroll
    for (int nt = 0; nt < 4; nt++) {
        const int n = n0 + wn * 32 + nt * 8 + 2 * tig;
        const float2 bn = *(const float2*)(bias + n);
        #pragma unroll
        for (int mt = 0; mt < MT; mt++) {
            const int r0 = m0 + wm * (MT * 16) + mt * 16 + gid;
            const int r1 = r0 + 8;
            float v0 = acc[mt][nt][0] + bn.x;
            float v1 = acc[mt][nt][1] + bn.y;
            float v2 = acc[mt][nt][2] + bn.x;
            float v3 = acc[mt][nt][3] + bn.y;
            if (EPI == 1) {
                const float2 q0 = *(const float2*)(res + (size_t)r0 * N + n);
                const float2 q1 = *(const float2*)(res + (size_t)r1 * N + n);
                v0 += q0.x; v1 += q0.y; v2 += q1.x; v3 += q1.y;
            }
            if (EPI == 2) {
                v0 = 0.5f * v0 * (1.0f + erff(v0 * 0.70710678118654752f));
                v1 = 0.5f * v1 * (1.0f + erff(v1 * 0.70710678118654752f));
                v2 = 0.5f * v2 * (1.0f + erff(v2 * 0.70710678118654752f));
                v3 = 0.5f * v3 * (1.0f + erff(v3 * 0.70710678118654752f));
            }
            if (OUTH) {
                *(__half2*)(outh + (size_t)r0 * N + n) = __floats2half2_rn(v0, v1);
                *(__half2*)(outh + (size_t)r1 * N + n) = __floats2half2_rn(v2, v3);
            } else {
                *(float2*)(outf + (size_t)r0 * N + n) = make_float2(v0, v1);
                *(float2*)(outf + (size_t)r1 * N + n) = make_float2(v2, v3);
            }
        }
    }
}

// ---------------- LayerNorm: warp-per-row, zero barriers ----------------
// 1024 blocks x 256 threads; warp w handles row blockIdx.x*8 + w.
// Lane loads 8 channels; sum/sumsq reduced via 10 shfl_xor; fp16 uint4 store.
__global__ void __launch_bounds__(256)
ln_kernel(const float* __restrict__ x,
          const float* __restrict__ w,
          const float* __restrict__ b,
          __half* __restrict__ out) {
    const int lane = threadIdx.x & 31;
    const int row  = blockIdx.x * 8 + (threadIdx.x >> 5);

    const float4* xp = (const float4*)(x + (size_t)row * CC) + lane * 2;
    const float4 a = xp[0];
    const float4 d = xp[1];

    float s = (a.x + a.y) + (a.z + a.w) + (d.x + d.y) + (d.z + d.w);
    float q = a.x * a.x + a.y * a.y + a.z * a.z + a.w * a.w
            + d.x * d.x + d.y * d.y + d.z * d.z + d.w * d.w;
    #pragma unroll
    for (int off = 16; off > 0; off >>= 1) {
        s += __shfl_xor_sync(0xFFFFFFFFu, s, off);
        q += __shfl_xor_sync(0xFFFFFFFFu, q, off);
    }
    const float m   = s * (1.0f / CC);
    const float var = q * (1.0f / CC) - m * m;
    const float r   = rsqrtf(var + 1e-5f);

    const float4* wp = (const float4*)w + lane * 2;
    const float4* bp = (const float4*)b + lane * 2;
    const float4 w0 = wp[0], w1 = wp[1];
    const float4 b0 = bp[0], b1 = bp[1];

    uint4 o;
    o.x = pack_h2((a.x - m) * r * w0.x + b0.x, (a.y - m) * r * w0.y + b0.y);
    o.y = pack_h2((a.z - m) * r * w0.z + b0.z, (a.w - m) * r * w0.w + b0.w);
    o.z = pack_h2((d.x - m) * r * w1.x + b1.x, (d.y - m) * r * w1.y + b1.y);
    o.w = pack_h2((d.z - m) * r * w1.z + b1.z, (d.w - m) * r * w1.w + b1.w);
    *(uint4*)(out + (size_t)row * CC + lane * 8) = o;
}

// ---------------- tiled neighborhood attention (R10: fp32 halos, fp32 compute) ----------------
// 128 blocks (one full wave), 512 threads; block = (16x16 tile, head PAIR, batch).
// Lane pairs (tx, tx+16) split the 32 head channels; one shfl combines scores.
#define TS    16
#define HALO  22          // TS + 6
#define NHPIX (HALO*HALO) // 484
#define PPITCH 36         // floats per halo pixel (32 data + 4 pad: bank spread)
#define NATT_SMEM (2 * NHPIX * PPITCH * 4)   // 139392 B

__global__ void __launch_bounds__(512)
natt_tile(const float* __restrict__ qkv, __half* __restrict__ out) {
    extern __shared__ float sm[];
    float* ks = sm;
    float* vs = sm + NHPIX * PPITCH;

    const int tile  = blockIdx.x;         // 0..15 (4x4 tiles)
    const int hpair = blockIdx.y;         // 0..3
    const int b     = blockIdx.z;
    const int ti0 = (tile >> 2) * TS;
    const int tj0 = (tile & 3) * TS;
    const int tid = threadIdx.x;

    const int lane = tid & 31;
    const int tx   = lane & 15;
    const int half = lane >> 4;           // channel half: 0 or 1
    const int ty   = tid >> 5;            // 0..15
    const int choff = half * 16;          // channel offset within head

    const int hbr = ti0 - 3;
    const int hbc = tj0 - 3;
    const int i = ti0 + ty;
    const int j = tj0 + tx;
    const size_t pix = (size_t)((b * HH + i) * WW + j);

    const int si = min(max(i - 3, 0), HH - KWIN);
    const int sj = min(max(j - 3, 0), WW - KWIN);
    const int lr0 = si - hbr;
    const int lc0 = sj - hbc;

    #pragma unroll
    for (int hp = 0; hp < 2; hp++) {
        const int head  = hpair * 2 + hp;
        const int hbase = head * HDIM;

        // ---- stage K and V halos for this head ----
        for (int idx = tid; idx < NHPIX * 8; idx += 512) {
            const int p  = idx >> 3;
            const int c  = idx & 7;
            const int hr = p / HALO;
            const int hc = p - hr * HALO;
            const int gr = min(max(hbr + hr, 0), HH - 1);
            const int gc = min(max(hbc + hc, 0), WW - 1);
            const size_t gpix = (size_t)((b * HH + gr) * WW + gc);
            const float* base = qkv + gpix * 768 + hbase;
            *(float4*)(ks + p * PPITCH + c * 4) = *(const float4*)(base + 256 + c * 4);
            *(float4*)(vs + p * PPITCH + c * 4) = *(const float4*)(base + 512 + c * 4);
        }

        // ---- q (this thread's 16 channels), pre-scaled; overlaps staging ----
        float4 q[4];
        const float4* qp = (const float4*)(qkv + pix * 768 + hbase + choff);
        #pragma unroll
        for (int c = 0; c < 4; c++) {
            q[c] = qp[c];
            q[c].x *= 0.17677669529663687f; q[c].y *= 0.17677669529663687f;
            q[c].z *= 0.17677669529663687f; q[c].w *= 0.17677669529663687f;
        }
        __syncthreads();

        // ---- QK: 49 half-scores, then pairwise combine via 1 shuffle each ----
        float sc[49];
        #pragma unroll
        for (int dr = 0; dr < 7; dr++) {
            const float* rowp = ks + (lr0 + dr) * (HALO * PPITCH) + lc0 * PPITCH + choff;
            #pragma unroll
            for (int dc = 0; dc < 7; dc++) {
                const float* kp = rowp + dc * PPITCH;
                float d0 = 0.f, d1 = 0.f, d2 = 0.f, d3 = 0.f;
                #pragma unroll
                for (int c = 0; c < 4; c++) {
                    float4 kv = *(const float4*)(kp + c * 4);
                    d0 = fmaf(q[c].x, kv.x, d0);
                    d1 = fmaf(q[c].y, kv.y, d1);
                    d2 = fmaf(q[c].z, kv.z, d2);
                    d3 = fmaf(q[c].w, kv.w, d3);
                }
                sc[dr * 7 + dc] = (d0 + d1) + (d2 + d3);
            }
        }
        #pragma unroll
        for (int n = 0; n < 49; n++)
            sc[n] += __shfl_xor_sync(0xFFFFFFFFu, sc[n], 16);

        // ---- softmax (in-thread; redundant across the lane pair) ----
        float m = sc[0];
        #pragma unroll
        for (int n = 1; n < 49; n++) m = fmaxf(m, sc[n]);
        float den = 0.f;
        #pragma unroll
        for (int n = 0; n < 49; n++) { sc[n] = __expf(sc[n] - m); den += sc[n]; }
        const float inv = 1.0f / den;

        // ---- AV over this thread's 16 channels ----
        float4 acc[4];
        #pragma unroll
        for (int c = 0; c < 4; c++) acc[c] = make_float4(0.f, 0.f, 0.f, 0.f);
        #pragma unroll
        for (int dr = 0; dr < 7; dr++) {
            const float* rowp = vs + (lr0 + dr) * (HALO * PPITCH) + lc0 * PPITCH + choff;
            #pragma unroll
            for (int dc = 0; dc < 7; dc++) {
                const float w = sc[dr * 7 + dc];
                const float* vp = rowp + dc * PPITCH;
                #pragma unroll
                for (int c = 0; c < 4; c++) {
                    float4 vv = *(const float4*)(vp + c * 4);
                    acc[c].x = fmaf(w, vv.x, acc[c].x);
                    acc[c].y = fmaf(w, vv.y, acc[c].y);
                    acc[c].z = fmaf(w, vv.z, acc[c].z);
                    acc[c].w = fmaf(w, vv.w, acc[c].w);
                }
            }
        }

        __half2* op = (__half2*)(out + pix * CC + hbase + choff);
        #pragma unroll
        for (int c = 0; c < 4; c++) {
            op[2 * c]     = __floats2half2_rn(acc[c].x * inv, acc[c].y * inv);
            op[2 * c + 1] = __floats2half2_rn(acc[c].z * inv, acc[c].w * inv);
        }
        if (hp == 0) __syncthreads();   // all reads done before restaging
    }
}

// ---------------- host launcher ----------------
extern "C" void kernel_launch(void* const* d_in, const int* in_sizes, int n_in,
                              void* d_out, int out_size) {
    const float* x      = (const float*)d_in[0];
    const float* ln1_w  = (const float*)d_in[1];
    const float* ln1_b  = (const float*)d_in[2];
    const float* qkv_w  = (const float*)d_in[3];
    const float* qkv_b  = (const float*)d_in[4];
    const float* proj_w = (const float*)d_in[5];
    const float* proj_b = (const float*)d_in[6];
    const float* ln2_w  = (const float*)d_in[7];
    const float* ln2_b  = (const float*)d_in[8];
    const float* fc1_w  = (const float*)d_in[9];
    const float* fc1_b  = (const float*)d_in[10];
    const float* fc2_w  = (const float*)d_in[11];
    const float* fc2_b  = (const float*)d_in[12];
    float* out = (float*)d_out;

    __half *xn, *attn, *hn, *h1, *wh;
    float *qkv;
    cudaGetSymbolAddress((void**)&xn,   g_xn);
    cudaGetSymbolAddress((void**)&qkv,  g_qkv);
    cudaGetSymbolAddress((void**)&attn, g_attn);
    cudaGetSymbolAddress((void**)&hn,   g_hn);
    cudaGetSymbolAddress((void**)&h1,   g_h1);
    cudaGetSymbolAddress((void**)&wh,   g_wh);

    const __half* wh_qkv  = wh;                      // 196608 halfs
    const __half* wh_proj = wh + 196608;             // 65536
    const __half* wh_fc1  = wh + 262144;             // 262144
    const __half* wh_fc2  = wh + 524288;             // 262144

    constexpr int SM128 = 3 * (TILE_A_H + 128 * TPH);  // 61440
    constexpr int SM64  = 3 * (TILE_A_H + 64  * TPH);  // 46080

    cudaFuncSetAttribute((const void*)gemm_tc<0,128,0>, cudaFuncAttributeMaxDynamicSharedMemorySize, SM128);
    cudaFuncSetAttribute((const void*)gemm_tc<2,128,1>, cudaFuncAttributeMaxDynamicSharedMemorySize, SM128);
    cudaFuncSetAttribute((const void*)gemm_tc<1,64,0>,  cudaFuncAttributeMaxDynamicSharedMemorySize, SM64);
    cudaFuncSetAttribute((const void*)natt_tile,        cudaFuncAttributeMaxDynamicSharedMemorySize, NATT_SMEM);

    // 0. convert all weights to fp16 (RN)
    round_weights<<<768, 256>>>((const float4*)qkv_w, (const float4*)proj_w,
                                (const float4*)fc1_w, (const float4*)fc2_w,
                                (__half2*)wh);

    // 1. LN1 -> fp16 (warp-per-row)
    ln_kernel<<<NPIX / 8, 256>>>(x, ln1_w, ln1_b, xn);

    // 2. QKV GEMM: [8192,256] x [768,256]^T -> fp32 (R10 config: BN=128)
    gemm_tc<0,128,0><<<dim3(768 / 128, NPIX / 128), 256, SM128>>>(
        xn, wh_qkv, qkv_b, nullptr, qkv, NPIX, 768, CC);

    // 3. tiled neighborhood attention (R10 kernel) -> fp16
    natt_tile<<<dim3(16, NHE / 2, BB), 512, NATT_SMEM>>>(qkv, attn);

    // 4. proj GEMM + bias + residual(x) -> fp32 d_out   (BN=64: 256 blocks)
    gemm_tc<1,64,0><<<dim3(CC / 64, NPIX / 128), 256, SM64>>>(
        attn, wh_proj, proj_b, x, out, NPIX, CC, CC);

    // 5. LN2 -> fp16 (warp-per-row)
    ln_kernel<<<NPIX / 8, 256>>>(out, ln2_w, ln2_b, hn);

    // 6. fc1 GEMM + exact GELU -> fp16
    gemm_tc<2,128,1><<<dim3(1024 / 128, NPIX / 128), 256, SM128>>>(
        hn, wh_fc1, fc1_b, nullptr, h1, NPIX, 1024, CC);

    // 7. fc2 GEMM + bias + residual(d_out) -> fp32 d_out   (BN=64: 256 blocks)
    gemm_tc<1,64,0><<<dim3(CC / 64, NPIX / 128), 256, SM64>>>(
        h1, wh_fc2, fc2_b, out, out, NPIX, CC, 1024);
}